// round 12
// baseline (speedup 1.0000x reference)
#include <cuda_runtime.h>
#include <cuda_bf16.h>

// Blur = UpFirDn2D(up=2, dn=2, k=4x4) collapses to a 2x2 stencil:
//   out[y][x] = f11*in[y][x] + f13*in[y][x+1] + f31*in[y+1][x] + f33*in[y+1][x+1]
// (zeros past the right/bottom edge).
//
// R10: retry R=8 rows/thread, this time with __launch_bounds__(256, 4) so
// ptxas has a 64-reg budget and keeps all 9 input rows live (the R3 attempt
// came back at regs=32: loads serialized into reused registers, MLP never
// deepened, and it regressed). Halo row address is clamped (no conditional
// load) so all 9 LDG.128 stay front-batched. Read redundancy 1.125x.

#define BB 8
#define CC 256
#define HH 128
#define WW 128
#define RR 8   // output rows per thread

__global__ __launch_bounds__(256, 4) void blur_kernel(
    const float* __restrict__ x,
    const float* __restrict__ filt,
    float* __restrict__ out)
{
    const int lane    = threadIdx.x & 31;
    const int warp_id = blockIdx.x * (blockDim.x >> 5) + (threadIdx.x >> 5);
    // warp -> (bc, row-group). Row groups per channel image: H/R = 16.
    const int rg = warp_id & 15;
    const int bc = warp_id >> 4;          // b*C + c
    const int c  = bc & (CC - 1);
    const int y0 = rg << 3;               // first output row of this group

    // Per-channel taps: uniform across the warp -> broadcast loads.
    const float* fp = filt + c * 16;
    const float w11 = __ldg(fp + 5);
    const float w13 = __ldg(fp + 7);
    const float w31 = __ldg(fp + 13);
    const float w33 = __ldg(fp + 15);

    const size_t base = ((size_t)bc << 14) + ((size_t)y0 << 7) + ((size_t)lane << 2);
    const float* p = x + base;

    // 9 unconditional front-batched LDG.128 into distinct named registers.
    // Last row-group: clamp the halo address in-bounds, zero it after.
    const bool last = (rg == 15);
    const int off8 = last ? (7 * WW) : (8 * WW);
    float4 r0 = *(const float4*)(p);
    float4 r1 = *(const float4*)(p + WW);
    float4 r2 = *(const float4*)(p + 2 * WW);
    float4 r3 = *(const float4*)(p + 3 * WW);
    float4 r4 = *(const float4*)(p + 4 * WW);
    float4 r5 = *(const float4*)(p + 5 * WW);
    float4 r6 = *(const float4*)(p + 6 * WW);
    float4 r7 = *(const float4*)(p + 7 * WW);
    float4 r8 = *(const float4*)(p + off8);
    if (last) r8 = make_float4(0.0f, 0.0f, 0.0f, 0.0f);

    // Next lane's .x = this thread's column x+4 neighbor. Lane 31 = image edge.
    float n0 = __shfl_down_sync(0xffffffffu, r0.x, 1);
    float n1 = __shfl_down_sync(0xffffffffu, r1.x, 1);
    float n2 = __shfl_down_sync(0xffffffffu, r2.x, 1);
    float n3 = __shfl_down_sync(0xffffffffu, r3.x, 1);
    float n4 = __shfl_down_sync(0xffffffffu, r4.x, 1);
    float n5 = __shfl_down_sync(0xffffffffu, r5.x, 1);
    float n6 = __shfl_down_sync(0xffffffffu, r6.x, 1);
    float n7 = __shfl_down_sync(0xffffffffu, r7.x, 1);
    float n8 = __shfl_down_sync(0xffffffffu, r8.x, 1);
    if (lane == 31) { n0=n1=n2=n3=n4=n5=n6=n7=n8=0.0f; }

    float* q = out + base;
    float4 o;

#define ROW(I, A, B, NA, NB)                                   \
    o.x = w11 * A.x + w13 * A.y + w31 * B.x + w33 * B.y;       \
    o.y = w11 * A.y + w13 * A.z + w31 * B.y + w33 * B.z;       \
    o.z = w11 * A.z + w13 * A.w + w31 * B.z + w33 * B.w;       \
    o.w = w11 * A.w + w13 * NA  + w31 * B.w + w33 * NB;        \
    *(float4*)(q + (I) * WW) = o;

    ROW(0, r0, r1, n0, n1)
    ROW(1, r1, r2, n1, n2)
    ROW(2, r2, r3, n2, n3)
    ROW(3, r3, r4, n3, n4)
    ROW(4, r4, r5, n4, n5)
    ROW(5, r5, r6, n5, n6)
    ROW(6, r6, r7, n6, n7)
    ROW(7, r7, r8, n7, n8)
#undef ROW
}

extern "C" void kernel_launch(void* const* d_in, const int* in_sizes, int n_in,
                              void* d_out, int out_size)
{
    const float* x    = (const float*)d_in[0];
    const float* filt = (const float*)d_in[1];
    float* out        = (float*)d_out;

    // warps = B*C*(H/R) = 2048*16 = 32768; 8 warps/block -> 4096 blocks
    const int block = 256;
    const int grid  = (BB * CC * (HH / RR) * 32) / block;
    blur_kernel<<<grid, block>>>(x, filt, out);
}